// round 1
// baseline (speedup 1.0000x reference)
#include <cuda_runtime.h>

#define HIDDEN    64
#define N_USERS   100000
#define N_MOVIES  50000
#define MOVIE_FEAT 128
#define N_EDGES   2000000
#define N_LABEL   500000

// padded so the single-block scans can read int4 past n without guards
#define NM_PAD (N_MOVIES + 8192)
#define NU_PAD (N_USERS  + 8192)

// ---------------- device scratch (allocation-free rule: __device__ globals) ----------------
__device__ __align__(16) int g_deg_m[NM_PAD];
__device__ __align__(16) int g_deg_u[NU_PAD];
__device__ __align__(16) int g_off_m[NM_PAD];
__device__ __align__(16) int g_off_u[NU_PAD];
__device__ int g_cur_m[N_MOVIES];
__device__ int g_cur_u[N_USERS];
__device__ int g_csr_m[N_EDGES];   // neighbors (user idx) of each movie, CSR by movie
__device__ int g_csr_u[N_EDGES];   // neighbors (movie idx) of each user, CSR by user
__device__ __align__(16) float g_xu[N_USERS  * HIDDEN];
__device__ __align__(16) float g_xm[N_MOVIES * HIDDEN];
__device__ __align__(16) float g_hu[N_USERS  * HIDDEN];
__device__ __align__(16) float g_hm[N_MOVIES * HIDDEN];
__device__ __align__(16) float g_mu[N_USERS  * HIDDEN];
__device__ __align__(16) float g_mm[N_MOVIES * HIDDEN];

// ---------------- CSR build ----------------
__global__ void zero_deg_kernel()
{
    int i = blockIdx.x * blockDim.x + threadIdx.x;
    if (i < NM_PAD) g_deg_m[i] = 0;
    if (i < NU_PAD) g_deg_u[i] = 0;
}

__global__ void hist_kernel(const int* __restrict__ src, const int* __restrict__ dst)
{
    int i = blockIdx.x * blockDim.x + threadIdx.x;
    if (i >= N_EDGES) return;
    atomicAdd(&g_deg_u[src[i]], 1);
    atomicAdd(&g_deg_m[dst[i]], 1);
}

// block 0 scans movie degrees, block 1 scans user degrees (both run concurrently)
__global__ __launch_bounds__(1024) void scan_kernel()
{
    int n; int* deg; int* off;
    if (blockIdx.x == 0) { n = N_MOVIES; deg = g_deg_m; off = g_off_m; }
    else                 { n = N_USERS;  deg = g_deg_u; off = g_off_u; }
    int chunk = ((((n + 1023) >> 10) + 3) & ~3);   // multiple of 4 for int4
    int t = threadIdx.x;
    int start = t * chunk;

    int s = 0;
    for (int i = 0; i < chunk; i += 4) {
        int4 v = *(const int4*)(deg + start + i);
        s += v.x + v.y + v.z + v.w;
    }
    __shared__ int sh[1024];
    sh[t] = s; __syncthreads();
    for (int d = 1; d < 1024; d <<= 1) {
        int v = (t >= d) ? sh[t - d] : 0;
        __syncthreads();
        sh[t] += v;
        __syncthreads();
    }
    int run = t ? sh[t - 1] : 0;
    for (int i = 0; i < chunk; i += 4) {
        int4 v = *(const int4*)(deg + start + i);
        int4 o;
        o.x = run; run += v.x;
        o.y = run; run += v.y;
        o.z = run; run += v.z;
        o.w = run; run += v.w;
        *(int4*)(off + start + i) = o;
    }
}

__global__ void cursor_kernel()
{
    int i = blockIdx.x * blockDim.x + threadIdx.x;
    if (i < N_MOVIES) g_cur_m[i] = g_off_m[i];
    if (i < N_USERS)  g_cur_u[i] = g_off_u[i];
}

__global__ void scatter_kernel(const int* __restrict__ src, const int* __restrict__ dst)
{
    int i = blockIdx.x * blockDim.x + threadIdx.x;
    if (i >= N_EDGES) return;
    int u = src[i], m = dst[i];
    g_csr_m[atomicAdd(&g_cur_m[m], 1)] = u;
    g_csr_u[atomicAdd(&g_cur_u[u], 1)] = m;
}

// ---------------- feature init ----------------
__global__ void gather_user_kernel(const float* __restrict__ emb,
                                   const int* __restrict__ nid,
                                   float* __restrict__ xu)
{
    int i = blockIdx.x * blockDim.x + threadIdx.x;   // over N_USERS*16 float4s
    if (i >= N_USERS * 16) return;
    int r = i >> 4, c = i & 15;
    ((float4*)xu)[i] = ((const float4*)emb)[nid[r] * 16 + c];
}

// x_movie = movie_x @ lin_W^T + lin_b + movie_emb[movie_nid]
__global__ __launch_bounds__(256) void movie_init_kernel(
    const float* __restrict__ movie_x, const float* __restrict__ lin_W,
    const float* __restrict__ lin_b,  const float* __restrict__ movie_emb,
    const int* __restrict__ movie_nid, float* __restrict__ xm, int n)
{
    __shared__ float4 srow[4][32];
    int j = threadIdx.x & 63, g = threadIdx.x >> 6;
    float w[128];
#pragma unroll
    for (int k = 0; k < 32; k++) {
        float4 t = ((const float4*)lin_W)[j * 32 + k];
        w[4*k] = t.x; w[4*k+1] = t.y; w[4*k+2] = t.z; w[4*k+3] = t.w;
    }
    float bj = lin_b[j];
    for (int r0 = blockIdx.x * 4; r0 < n; r0 += gridDim.x * 4) {
        int r = r0 + g;
        if (r < n && j < 32) srow[g][j] = ((const float4*)(movie_x + (size_t)r * 128))[j];
        __syncthreads();
        if (r < n) {
            float a0 = 0, a1 = 0, a2 = 0, a3 = 0;
#pragma unroll
            for (int k = 0; k < 32; k++) {
                float4 v = srow[g][k];
                a0 = fmaf(v.x, w[4*k],   a0);
                a1 = fmaf(v.y, w[4*k+1], a1);
                a2 = fmaf(v.z, w[4*k+2], a2);
                a3 = fmaf(v.w, w[4*k+3], a3);
            }
            xm[r * 64 + j] = (a0 + a1) + (a2 + a3) + bj + movie_emb[movie_nid[r] * 64 + j];
        }
        __syncthreads();
    }
}

// ---------------- segment mean (CSR gather, warp per node, float2 per lane) ----------------
__global__ void aggregate_kernel(const float* __restrict__ xsrc,
                                 const int* __restrict__ csr,
                                 const int* __restrict__ off,
                                 float* __restrict__ mean, int n)
{
    int w = (blockIdx.x * blockDim.x + threadIdx.x) >> 5;
    int lane = threadIdx.x & 31;
    if (w >= n) return;
    int s0 = off[w], s1 = off[w + 1];
    int deg = s1 - s0;
    const int* nb = csr + s0;
    float ax = 0, ay = 0, bx = 0, by = 0;
    int i = 0;
    for (; i + 4 <= deg; i += 4) {
        int n0 = __ldg(nb + i),     n1 = __ldg(nb + i + 1);
        int n2 = __ldg(nb + i + 2), n3 = __ldg(nb + i + 3);
        float2 v0 = *(const float2*)(xsrc + n0 * 64 + 2 * lane);
        float2 v1 = *(const float2*)(xsrc + n1 * 64 + 2 * lane);
        float2 v2 = *(const float2*)(xsrc + n2 * 64 + 2 * lane);
        float2 v3 = *(const float2*)(xsrc + n3 * 64 + 2 * lane);
        ax += v0.x; ay += v0.y;
        bx += v1.x; by += v1.y;
        ax += v2.x; ay += v2.y;
        bx += v3.x; by += v3.y;
    }
    for (; i < deg; i++) {
        int n0 = __ldg(nb + i);
        float2 v = *(const float2*)(xsrc + n0 * 64 + 2 * lane);
        ax += v.x; ay += v.y;
    }
    float inv = deg > 0 ? 1.0f / (float)deg : 0.0f;   // matches max(cnt,1); deg==0 -> agg==0
    float2 o; o.x = (ax + bx) * inv; o.y = (ay + by) * inv;
    *(float2*)(mean + (size_t)w * 64 + 2 * lane) = o;
}

// ---------------- SAGE transform: out = mean@Wl^T + bl + x@Wr^T (opt relu) ----------------
template<bool RELU>
__global__ __launch_bounds__(256) void transform_kernel(
    const float* __restrict__ mean, const float* __restrict__ xdst,
    const float* __restrict__ Wl,   const float* __restrict__ bl,
    const float* __restrict__ Wr,   float* __restrict__ out, int n)
{
    __shared__ float4 sm[4][2][16];
    int j = threadIdx.x & 63, g = threadIdx.x >> 6;
    float wl[64], wr[64];
#pragma unroll
    for (int k = 0; k < 16; k++) {
        float4 a = ((const float4*)Wl)[j * 16 + k];
        wl[4*k] = a.x; wl[4*k+1] = a.y; wl[4*k+2] = a.z; wl[4*k+3] = a.w;
        float4 b = ((const float4*)Wr)[j * 16 + k];
        wr[4*k] = b.x; wr[4*k+1] = b.y; wr[4*k+2] = b.z; wr[4*k+3] = b.w;
    }
    float bj = bl[j];
    for (int r0 = blockIdx.x * 4; r0 < n; r0 += gridDim.x * 4) {
        int r = r0 + g;
        if (r < n) {
            if (j < 16)      sm[g][0][j]      = ((const float4*)(mean + (size_t)r * 64))[j];
            else if (j < 32) sm[g][1][j - 16] = ((const float4*)(xdst + (size_t)r * 64))[j - 16];
        }
        __syncthreads();
        if (r < n) {
            float a0 = 0, a1 = 0, a2 = 0, a3 = 0;
#pragma unroll
            for (int k = 0; k < 16; k++) {
                float4 m = sm[g][0][k], x = sm[g][1][k];
                a0 = fmaf(m.x, wl[4*k],   a0); a1 = fmaf(m.y, wl[4*k+1], a1);
                a2 = fmaf(m.z, wl[4*k+2], a2); a3 = fmaf(m.w, wl[4*k+3], a3);
                a0 = fmaf(x.x, wr[4*k],   a0); a1 = fmaf(x.y, wr[4*k+1], a1);
                a2 = fmaf(x.z, wr[4*k+2], a2); a3 = fmaf(x.w, wr[4*k+3], a3);
            }
            float res = bj + ((a0 + a1) + (a2 + a3));
            if (RELU) res = fmaxf(res, 0.0f);
            out[(size_t)r * 64 + j] = res;
        }
        __syncthreads();
    }
}

// ---------------- dot-product decoder ----------------
__global__ void decode_kernel(const float* __restrict__ ou, const float* __restrict__ om,
                              const int* __restrict__ ls, const int* __restrict__ ld,
                              float* __restrict__ out, int n)
{
    int e = (blockIdx.x * blockDim.x + threadIdx.x) >> 5;
    int lane = threadIdx.x & 31;
    if (e >= n) return;
    int u = __ldg(ls + e), m = __ldg(ld + e);
    float2 a = *(const float2*)(ou + (size_t)u * 64 + 2 * lane);
    float2 b = *(const float2*)(om + (size_t)m * 64 + 2 * lane);
    float p = a.x * b.x + a.y * b.y;
#pragma unroll
    for (int o = 16; o > 0; o >>= 1) p += __shfl_xor_sync(0xffffffffu, p, o);
    if (lane == 0) out[e] = p;
}

// ---------------- launch ----------------
extern "C" void kernel_launch(void* const* d_in, const int* in_sizes, int n_in,
                              void* d_out, int out_size)
{
    const float* movie_x   = (const float*)d_in[0];
    const int*   user_nid  = (const int*)d_in[1];
    const int*   movie_nid = (const int*)d_in[2];
    const int*   e_src     = (const int*)d_in[3];
    const int*   e_dst     = (const int*)d_in[4];
    const int*   l_src     = (const int*)d_in[5];
    const int*   l_dst     = (const int*)d_in[6];
    const float* user_emb  = (const float*)d_in[7];
    const float* movie_emb = (const float*)d_in[8];
    const float* lin_W     = (const float*)d_in[9];
    const float* lin_b     = (const float*)d_in[10];
    const float* W_l_um1 = (const float*)d_in[11];
    const float* b_l_um1 = (const float*)d_in[12];
    const float* W_r_um1 = (const float*)d_in[13];
    const float* W_l_mu1 = (const float*)d_in[14];
    const float* b_l_mu1 = (const float*)d_in[15];
    const float* W_r_mu1 = (const float*)d_in[16];
    const float* W_l_um2 = (const float*)d_in[17];
    const float* b_l_um2 = (const float*)d_in[18];
    const float* W_r_um2 = (const float*)d_in[19];
    const float* W_l_mu2 = (const float*)d_in[20];
    const float* b_l_mu2 = (const float*)d_in[21];
    const float* W_r_mu2 = (const float*)d_in[22];
    float* out = (float*)d_out;

    float *xu, *xm, *hu, *hm, *mu, *mm;
    int *csr_m, *csr_u, *off_m, *off_u;
    cudaGetSymbolAddress((void**)&xu, g_xu);
    cudaGetSymbolAddress((void**)&xm, g_xm);
    cudaGetSymbolAddress((void**)&hu, g_hu);
    cudaGetSymbolAddress((void**)&hm, g_hm);
    cudaGetSymbolAddress((void**)&mu, g_mu);
    cudaGetSymbolAddress((void**)&mm, g_mm);
    cudaGetSymbolAddress((void**)&csr_m, g_csr_m);
    cudaGetSymbolAddress((void**)&csr_u, g_csr_u);
    cudaGetSymbolAddress((void**)&off_m, g_off_m);
    cudaGetSymbolAddress((void**)&off_u, g_off_u);

    // CSR build (reused by both layers, both directions)
    zero_deg_kernel<<<(NU_PAD + 255) / 256, 256>>>();
    hist_kernel<<<(N_EDGES + 255) / 256, 256>>>(e_src, e_dst);
    scan_kernel<<<2, 1024>>>();
    cursor_kernel<<<(N_USERS + 255) / 256, 256>>>();
    scatter_kernel<<<(N_EDGES + 255) / 256, 256>>>(e_src, e_dst);

    // feature init
    gather_user_kernel<<<(N_USERS * 16 + 255) / 256, 256>>>(user_emb, user_nid, xu);
    movie_init_kernel<<<592, 256>>>(movie_x, lin_W, lin_b, movie_emb, movie_nid, xm, N_MOVIES);

    // layer 1 (+relu)
    aggregate_kernel<<<(N_MOVIES + 7) / 8, 256>>>(xu, csr_m, off_m, mm, N_MOVIES);
    aggregate_kernel<<<(N_USERS + 7) / 8, 256>>>(xm, csr_u, off_u, mu, N_USERS);
    transform_kernel<true><<<592, 256>>>(mm, xm, W_l_um1, b_l_um1, W_r_um1, hm, N_MOVIES);
    transform_kernel<true><<<592, 256>>>(mu, xu, W_l_mu1, b_l_mu1, W_r_mu1, hu, N_USERS);

    // layer 2 (no activation); outputs overwrite x buffers
    aggregate_kernel<<<(N_MOVIES + 7) / 8, 256>>>(hu, csr_m, off_m, mm, N_MOVIES);
    aggregate_kernel<<<(N_USERS + 7) / 8, 256>>>(hm, csr_u, off_u, mu, N_USERS);
    transform_kernel<false><<<592, 256>>>(mm, hm, W_l_um2, b_l_um2, W_r_um2, xm, N_MOVIES);
    transform_kernel<false><<<592, 256>>>(mu, hu, W_l_mu2, b_l_mu2, W_r_mu2, xu, N_USERS);

    // decoder
    decode_kernel<<<(N_LABEL + 7) / 8, 256>>>(xu, xm, l_src, l_dst, out, N_LABEL);
}

// round 2
// speedup vs baseline: 1.6766x; 1.6766x over previous
#include <cuda_runtime.h>

#define HIDDEN    64
#define N_USERS   100000
#define N_MOVIES  50000
#define MOVIE_FEAT 128
#define N_EDGES   2000000
#define N_LABEL   500000

// padded so the single-block scans can read int4 past n without guards
#define NM_PAD (N_MOVIES + 8192)
#define NU_PAD (N_USERS  + 8192)

// ---------------- device scratch (allocation-free rule: __device__ globals) ----------------
__device__ __align__(16) int g_deg_m[NM_PAD];
__device__ __align__(16) int g_deg_u[NU_PAD];
__device__ __align__(16) int g_off_m[NM_PAD];
__device__ __align__(16) int g_off_u[NU_PAD];
__device__ __align__(16) int g_cur_m[NM_PAD];
__device__ __align__(16) int g_cur_u[NU_PAD];
__device__ int g_csr_m[N_EDGES];   // neighbors (user idx) of each movie, CSR by movie
__device__ int g_csr_u[N_EDGES];   // neighbors (movie idx) of each user, CSR by user
__device__ __align__(16) float g_xu[N_USERS  * HIDDEN];
__device__ __align__(16) float g_xm[N_MOVIES * HIDDEN];
__device__ __align__(16) float g_hu[N_USERS  * HIDDEN];
__device__ __align__(16) float g_hm[N_MOVIES * HIDDEN];
__device__ __align__(16) float g_mu[N_USERS  * HIDDEN];
__device__ __align__(16) float g_mm[N_MOVIES * HIDDEN];

// ---------------- CSR build ----------------
__global__ void zero_deg_kernel()
{
    int i = blockIdx.x * blockDim.x + threadIdx.x;
    int4 z = make_int4(0, 0, 0, 0);
    if (i < NM_PAD / 4) ((int4*)g_deg_m)[i] = z;
    if (i < NU_PAD / 4) ((int4*)g_deg_u)[i] = z;
}

__global__ void hist_kernel(const int* __restrict__ src, const int* __restrict__ dst)
{
    int i = blockIdx.x * blockDim.x + threadIdx.x;
    if (i >= N_EDGES) return;
    atomicAdd(&g_deg_u[src[i]], 1);
    atomicAdd(&g_deg_m[dst[i]], 1);
}

// block 0 scans movie degrees, block 1 scans user degrees; also initializes cursors
__global__ __launch_bounds__(1024) void scan_kernel()
{
    int n; int* deg; int* off; int* cur;
    if (blockIdx.x == 0) { n = N_MOVIES; deg = g_deg_m; off = g_off_m; cur = g_cur_m; }
    else                 { n = N_USERS;  deg = g_deg_u; off = g_off_u; cur = g_cur_u; }
    int chunk = ((((n + 1023) >> 10) + 3) & ~3);   // multiple of 4 for int4
    int t = threadIdx.x;
    int start = t * chunk;

    int s = 0;
    for (int i = 0; i < chunk; i += 4) {
        int4 v = *(const int4*)(deg + start + i);
        s += v.x + v.y + v.z + v.w;
    }
    __shared__ int sh[1024];
    sh[t] = s; __syncthreads();
    for (int d = 1; d < 1024; d <<= 1) {
        int v = (t >= d) ? sh[t - d] : 0;
        __syncthreads();
        sh[t] += v;
        __syncthreads();
    }
    int run = t ? sh[t - 1] : 0;
    for (int i = 0; i < chunk; i += 4) {
        int4 v = *(const int4*)(deg + start + i);
        int4 o;
        o.x = run; run += v.x;
        o.y = run; run += v.y;
        o.z = run; run += v.z;
        o.w = run; run += v.w;
        *(int4*)(off + start + i) = o;
        *(int4*)(cur + start + i) = o;
    }
}

__global__ void scatter_kernel(const int* __restrict__ src, const int* __restrict__ dst)
{
    int i = blockIdx.x * blockDim.x + threadIdx.x;
    if (i >= N_EDGES) return;
    int u = src[i], m = dst[i];
    g_csr_m[atomicAdd(&g_cur_m[m], 1)] = u;
    g_csr_u[atomicAdd(&g_cur_u[u], 1)] = m;
}

// ---------------- feature init ----------------
__global__ void gather_user_kernel(const float* __restrict__ emb,
                                   const int* __restrict__ nid,
                                   float* __restrict__ xu)
{
    int i = blockIdx.x * blockDim.x + threadIdx.x;   // over N_USERS*16 float4s
    if (i >= N_USERS * 16) return;
    int r = i >> 4, c = i & 15;
    ((float4*)xu)[i] = __ldg((const float4*)emb + nid[r] * 16 + c);
}

// x_movie = movie_x @ lin_W^T + lin_b + movie_emb[movie_nid]
// 256 threads = 4 groups of 64; each group does 8 rows per iteration.
__global__ __launch_bounds__(256) void movie_init_kernel(
    const float* __restrict__ movie_x, const float* __restrict__ lin_W,
    const float* __restrict__ lin_b,  const float* __restrict__ movie_emb,
    const int* __restrict__ movie_nid, float* __restrict__ xm, int n)
{
    __shared__ float4 srow[4][8][32];
    int j = threadIdx.x & 63, g = threadIdx.x >> 6;
    float w[128];
#pragma unroll
    for (int k = 0; k < 32; k++) {
        float4 t = __ldg((const float4*)lin_W + j * 32 + k);
        w[4*k] = t.x; w[4*k+1] = t.y; w[4*k+2] = t.z; w[4*k+3] = t.w;
    }
    float bj = __ldg(lin_b + j);
    for (int r0 = blockIdx.x * 32; r0 < n; r0 += gridDim.x * 32) {
        int rbase = r0 + g * 8;
        // 8 rows x 32 float4 = 256 items per group, 4 per thread
#pragma unroll
        for (int p = 0; p < 4; p++) {
            int item = p * 64 + j;
            int row = item >> 5, col = item & 31;
            int r = rbase + row;
            if (r < n)
                srow[g][row][col] = __ldg((const float4*)movie_x + (size_t)r * 32 + col);
        }
        __syncthreads();
#pragma unroll
        for (int rr = 0; rr < 8; rr++) {
            int r = rbase + rr;
            if (r < n) {
                float a0 = 0, a1 = 0, a2 = 0, a3 = 0;
#pragma unroll
                for (int k = 0; k < 32; k++) {
                    float4 v = srow[g][rr][k];
                    a0 = fmaf(v.x, w[4*k],   a0);
                    a1 = fmaf(v.y, w[4*k+1], a1);
                    a2 = fmaf(v.z, w[4*k+2], a2);
                    a3 = fmaf(v.w, w[4*k+3], a3);
                }
                int nid = __ldg(movie_nid + r);
                xm[(size_t)r * 64 + j] =
                    (a0 + a1) + (a2 + a3) + bj + __ldg(movie_emb + (size_t)nid * 64 + j);
            }
        }
        __syncthreads();
    }
}

// ---------------- segment mean, both directions fused (half-warp per node, float4) --------
__global__ void aggregate2_kernel(const float* __restrict__ src_for_m,  // user feats
                                  const float* __restrict__ src_for_u,  // movie feats
                                  float* __restrict__ out_m, float* __restrict__ out_u)
{
    int h = (blockIdx.x * blockDim.x + threadIdx.x) >> 4;
    int lane = threadIdx.x & 15;
    const float4* xsrc; const int* csr; const int* off; float* mean; int node;
    if (h < N_MOVIES) {
        node = h; xsrc = (const float4*)src_for_m; csr = g_csr_m; off = g_off_m; mean = out_m;
    } else {
        node = h - N_MOVIES;
        if (node >= N_USERS) return;
        xsrc = (const float4*)src_for_u; csr = g_csr_u; off = g_off_u; mean = out_u;
    }
    int s0 = __ldg(off + node), s1 = __ldg(off + node + 1);
    int deg = s1 - s0;
    const int* nb = csr + s0;
    float ax = 0, ay = 0, az = 0, aw = 0;
    float bx = 0, by = 0, bz = 0, bw = 0;
    int i = 0;
    for (; i + 4 <= deg; i += 4) {
        int n0 = __ldg(nb + i),     n1 = __ldg(nb + i + 1);
        int n2 = __ldg(nb + i + 2), n3 = __ldg(nb + i + 3);
        float4 v0 = __ldg(xsrc + n0 * 16 + lane);
        float4 v1 = __ldg(xsrc + n1 * 16 + lane);
        float4 v2 = __ldg(xsrc + n2 * 16 + lane);
        float4 v3 = __ldg(xsrc + n3 * 16 + lane);
        ax += v0.x; ay += v0.y; az += v0.z; aw += v0.w;
        bx += v1.x; by += v1.y; bz += v1.z; bw += v1.w;
        ax += v2.x; ay += v2.y; az += v2.z; aw += v2.w;
        bx += v3.x; by += v3.y; bz += v3.z; bw += v3.w;
    }
    for (; i < deg; i++) {
        int n0 = __ldg(nb + i);
        float4 v = __ldg(xsrc + n0 * 16 + lane);
        ax += v.x; ay += v.y; az += v.z; aw += v.w;
    }
    float inv = deg > 0 ? 1.0f / (float)deg : 0.0f;   // deg==0 -> mean 0, matches reference
    float4 o;
    o.x = (ax + bx) * inv; o.y = (ay + by) * inv;
    o.z = (az + bz) * inv; o.w = (aw + bw) * inv;
    ((float4*)mean)[node * 16 + lane] = o;
}

// ---------------- SAGE transform, both edge types fused into one launch ----------------
// out = mean@Wl^T + bl + x@Wr^T (optional relu). 4 groups x 8 rows per block-iteration.
template<bool RELU>
__global__ __launch_bounds__(256) void transform2_kernel(
    const float* __restrict__ mean_m, const float* __restrict__ xd_m,
    const float* __restrict__ Wl_m, const float* __restrict__ bl_m,
    const float* __restrict__ Wr_m, float* __restrict__ out_m,
    const float* __restrict__ mean_u, const float* __restrict__ xd_u,
    const float* __restrict__ Wl_u, const float* __restrict__ bl_u,
    const float* __restrict__ Wr_u, float* __restrict__ out_u,
    int nb_m)
{
    __shared__ float4 sm[4][8][2][16];
    const float *mean, *xd, *Wl, *bl, *Wr; float* out; int n, bid, nb;
    if ((int)blockIdx.x < nb_m) {
        mean = mean_m; xd = xd_m; Wl = Wl_m; bl = bl_m; Wr = Wr_m; out = out_m;
        n = N_MOVIES; bid = blockIdx.x; nb = nb_m;
    } else {
        mean = mean_u; xd = xd_u; Wl = Wl_u; bl = bl_u; Wr = Wr_u; out = out_u;
        n = N_USERS; bid = blockIdx.x - nb_m; nb = gridDim.x - nb_m;
    }
    int j = threadIdx.x & 63, g = threadIdx.x >> 6;
    float wl[64], wr[64];
#pragma unroll
    for (int k = 0; k < 16; k++) {
        float4 a = __ldg((const float4*)Wl + j * 16 + k);
        wl[4*k] = a.x; wl[4*k+1] = a.y; wl[4*k+2] = a.z; wl[4*k+3] = a.w;
        float4 b = __ldg((const float4*)Wr + j * 16 + k);
        wr[4*k] = b.x; wr[4*k+1] = b.y; wr[4*k+2] = b.z; wr[4*k+3] = b.w;
    }
    float bj = __ldg(bl + j);
    for (int r0 = bid * 32; r0 < n; r0 += nb * 32) {
        int rbase = r0 + g * 8;
        // 8 rows x (16 mean f4 + 16 x f4) = 256 items per group, 4 per thread
#pragma unroll
        for (int p = 0; p < 4; p++) {
            int item = p * 64 + j;
            int row = item >> 5, sel = (item >> 4) & 1, col = item & 15;
            int r = rbase + row;
            if (r < n) {
                const float* src = sel ? xd : mean;
                sm[g][row][sel][col] = __ldg((const float4*)src + (size_t)r * 16 + col);
            }
        }
        __syncthreads();
#pragma unroll
        for (int rr = 0; rr < 8; rr++) {
            int r = rbase + rr;
            if (r < n) {
                float a0 = 0, a1 = 0, a2 = 0, a3 = 0;
#pragma unroll
                for (int k = 0; k < 16; k++) {
                    float4 m = sm[g][rr][0][k], x = sm[g][rr][1][k];
                    a0 = fmaf(m.x, wl[4*k],   a0); a1 = fmaf(m.y, wl[4*k+1], a1);
                    a2 = fmaf(m.z, wl[4*k+2], a2); a3 = fmaf(m.w, wl[4*k+3], a3);
                    a0 = fmaf(x.x, wr[4*k],   a0); a1 = fmaf(x.y, wr[4*k+1], a1);
                    a2 = fmaf(x.z, wr[4*k+2], a2); a3 = fmaf(x.w, wr[4*k+3], a3);
                }
                float res = bj + ((a0 + a1) + (a2 + a3));
                if (RELU) res = fmaxf(res, 0.0f);
                out[(size_t)r * 64 + j] = res;
            }
        }
        __syncthreads();
    }
}

// ---------------- dot-product decoder (half-warp per edge, float4) ----------------
__global__ void decode_kernel(const float* __restrict__ ou, const float* __restrict__ om,
                              const int* __restrict__ ls, const int* __restrict__ ld,
                              float* __restrict__ out, int n)
{
    int e = (blockIdx.x * blockDim.x + threadIdx.x) >> 4;
    int lane = threadIdx.x & 15;
    if (e >= n) return;
    int u = __ldg(ls + e), m = __ldg(ld + e);
    float4 a = __ldg((const float4*)ou + u * 16 + lane);
    float4 b = __ldg((const float4*)om + m * 16 + lane);
    float p = a.x * b.x + a.y * b.y + a.z * b.z + a.w * b.w;
    p += __shfl_xor_sync(0xffffffffu, p, 1);
    p += __shfl_xor_sync(0xffffffffu, p, 2);
    p += __shfl_xor_sync(0xffffffffu, p, 4);
    p += __shfl_xor_sync(0xffffffffu, p, 8);
    if (lane == 0) out[e] = p;
}

// ---------------- launch ----------------
extern "C" void kernel_launch(void* const* d_in, const int* in_sizes, int n_in,
                              void* d_out, int out_size)
{
    const float* movie_x   = (const float*)d_in[0];
    const int*   user_nid  = (const int*)d_in[1];
    const int*   movie_nid = (const int*)d_in[2];
    const int*   e_src     = (const int*)d_in[3];
    const int*   e_dst     = (const int*)d_in[4];
    const int*   l_src     = (const int*)d_in[5];
    const int*   l_dst     = (const int*)d_in[6];
    const float* user_emb  = (const float*)d_in[7];
    const float* movie_emb = (const float*)d_in[8];
    const float* lin_W     = (const float*)d_in[9];
    const float* lin_b     = (const float*)d_in[10];
    const float* W_l_um1 = (const float*)d_in[11];
    const float* b_l_um1 = (const float*)d_in[12];
    const float* W_r_um1 = (const float*)d_in[13];
    const float* W_l_mu1 = (const float*)d_in[14];
    const float* b_l_mu1 = (const float*)d_in[15];
    const float* W_r_mu1 = (const float*)d_in[16];
    const float* W_l_um2 = (const float*)d_in[17];
    const float* b_l_um2 = (const float*)d_in[18];
    const float* W_r_um2 = (const float*)d_in[19];
    const float* W_l_mu2 = (const float*)d_in[20];
    const float* b_l_mu2 = (const float*)d_in[21];
    const float* W_r_mu2 = (const float*)d_in[22];
    float* out = (float*)d_out;

    float *xu, *xm, *hu, *hm, *mu, *mm;
    cudaGetSymbolAddress((void**)&xu, g_xu);
    cudaGetSymbolAddress((void**)&xm, g_xm);
    cudaGetSymbolAddress((void**)&hu, g_hu);
    cudaGetSymbolAddress((void**)&hm, g_hm);
    cudaGetSymbolAddress((void**)&mu, g_mu);
    cudaGetSymbolAddress((void**)&mm, g_mm);

    // CSR build (reused by both layers, both directions)
    zero_deg_kernel<<<(NU_PAD / 4 + 255) / 256, 256>>>();
    hist_kernel<<<(N_EDGES + 255) / 256, 256>>>(e_src, e_dst);
    scan_kernel<<<2, 1024>>>();   // also writes cursors
    scatter_kernel<<<(N_EDGES + 255) / 256, 256>>>(e_src, e_dst);

    // feature init
    gather_user_kernel<<<(N_USERS * 16 + 255) / 256, 256>>>(user_emb, user_nid, xu);
    movie_init_kernel<<<592, 256>>>(movie_x, lin_W, lin_b, movie_emb, movie_nid, xm, N_MOVIES);

    const int AGG_BLOCKS = ((N_MOVIES + N_USERS) * 16 + 255) / 256;

    // layer 1 (+relu)
    aggregate2_kernel<<<AGG_BLOCKS, 256>>>(xu, xm, mm, mu);
    transform2_kernel<true><<<592, 256>>>(mm, xm, W_l_um1, b_l_um1, W_r_um1, hm,
                                          mu, xu, W_l_mu1, b_l_mu1, W_r_mu1, hu, 197);

    // layer 2 (no activation); outputs overwrite x buffers
    aggregate2_kernel<<<AGG_BLOCKS, 256>>>(hu, hm, mm, mu);
    transform2_kernel<false><<<592, 256>>>(mm, hm, W_l_um2, b_l_um2, W_r_um2, xm,
                                           mu, hu, W_l_mu2, b_l_mu2, W_r_mu2, xu, 197);

    // decoder
    decode_kernel<<<(N_LABEL * 16 + 255) / 256, 256>>>(xu, xm, l_src, l_dst, out, N_LABEL);
}